// round 3
// baseline (speedup 1.0000x reference)
#include <cuda_runtime.h>
#include <cuda_bf16.h>
#include <math.h>

// ---------------------------------------------------------------------------
// Problem constants (fixed by setup_inputs)
// ---------------------------------------------------------------------------
#define BATCH   4
#define SEQ     2048
#define DMODEL  1024
#define DINNER  2048
#define DSTATE  16
#define DCONV   4
#define MROWS   (BATCH * SEQ)          // 8192

// ---------------------------------------------------------------------------
// Scratch buffers (static device globals: allocation-free per harness rules)
// ---------------------------------------------------------------------------
__device__ float g_xz [MROWS * 2 * DINNER];   // (B*L, 4096)  in_proj output
__device__ float g_xc [MROWS * DINNER];       // (B*L, 2048)  conv+silu output
__device__ float g_dt [MROWS * DINNER];       // (B*L, 2048)  softplus(dt)
__device__ float g_bdt[MROWS * 2 * DSTATE];   // (B*L, 32)    [B | C]
__device__ float g_u  [MROWS * DINNER];       // (B*L, 2048)  y * silu(z)

// ---------------------------------------------------------------------------
// Tiled fp32 GEMM:  C(M,N) = A(M,K) @ B(K,N), all row-major.
// 128x128 block tile, BK=8, 256 threads, 8x8 register tile, reg prefetch.
// MODE 0: plain store.  MODE 1: softplus(acc + bias[n]).
// Requires M%128==0, N%128==0, K%8==0 (true for all calls here).
// ---------------------------------------------------------------------------
template<int MODE>
__global__ __launch_bounds__(256)
void gemm_kernel(const float* __restrict__ A, const float* __restrict__ B,
                 float* __restrict__ C, int M, int N, int K,
                 const float* __restrict__ bias)
{
    __shared__ float As[8][128];
    __shared__ float Bs[8][128];

    const int tid = threadIdx.x;
    const int tx  = tid & 15;          // 0..15  -> N direction
    const int ty  = tid >> 4;          // 0..15  -> M direction
    const int n0  = blockIdx.x * 128;
    const int m0  = blockIdx.y * 128;

    // A-tile loader mapping: 128 rows x 8 cols, one float4 per thread
    const int arow = tid >> 1;               // 0..127
    const int acol = (tid & 1) * 4;          // 0 or 4
    // B-tile loader mapping: 8 rows x 128 cols, one float4 per thread
    const int brow = tid >> 5;               // 0..7
    const int bcol = (tid & 31) * 4;         // 0..124

    const float* Aptr = A + (size_t)(m0 + arow) * K + acol;
    const float* Bptr = B + (size_t)brow * N + n0 + bcol;

    float acc[8][8];
    #pragma unroll
    for (int i = 0; i < 8; i++)
        #pragma unroll
        for (int j = 0; j < 8; j++) acc[i][j] = 0.f;

    // prime the prefetch registers
    float4 av = *(const float4*)Aptr;  Aptr += 8;
    float4 bv = *(const float4*)Bptr;  Bptr += (size_t)8 * N;

    const int ktiles = K >> 3;
    for (int kt = 0; kt < ktiles; kt++) {
        // stage current tile to smem
        As[acol + 0][arow] = av.x;
        As[acol + 1][arow] = av.y;
        As[acol + 2][arow] = av.z;
        As[acol + 3][arow] = av.w;
        *(float4*)&Bs[brow][bcol] = bv;
        __syncthreads();

        // prefetch next tile while computing
        if (kt + 1 < ktiles) {
            av = *(const float4*)Aptr;  Aptr += 8;
            bv = *(const float4*)Bptr;  Bptr += (size_t)8 * N;
        }

        #pragma unroll
        for (int k = 0; k < 8; k++) {
            float a[8], b[8];
            *(float4*)&a[0] = *(const float4*)&As[k][ty * 8];
            *(float4*)&a[4] = *(const float4*)&As[k][ty * 8 + 4];
            *(float4*)&b[0] = *(const float4*)&Bs[k][tx * 8];
            *(float4*)&b[4] = *(const float4*)&Bs[k][tx * 8 + 4];
            #pragma unroll
            for (int i = 0; i < 8; i++)
                #pragma unroll
                for (int j = 0; j < 8; j++)
                    acc[i][j] = fmaf(a[i], b[j], acc[i][j]);
        }
        __syncthreads();
    }

    // epilogue
    #pragma unroll
    for (int i = 0; i < 8; i++) {
        const int m = m0 + ty * 8 + i;
        float* Crow = C + (size_t)m * N + n0 + tx * 8;
        #pragma unroll
        for (int j = 0; j < 8; j++) {
            float v = acc[i][j];
            if (MODE == 1) {
                v += bias[n0 + tx * 8 + j];
                v = (v > 20.f) ? v : log1pf(expf(v));   // softplus
            }
            Crow[j] = v;
        }
    }
}

// ---------------------------------------------------------------------------
// Causal depthwise conv1d (k=4) + bias + SiLU over x_inner = g_xz[:, :2048]
// One thread per (m, d). xc[m,d] = silu(sum_j w[d,j]*xin[m-3+j, d] + b[d])
// ---------------------------------------------------------------------------
__global__ __launch_bounds__(256)
void conv_silu_kernel(const float* __restrict__ conv_w,
                      const float* __restrict__ conv_b)
{
    const int idx = blockIdx.x * blockDim.x + threadIdx.x;   // 0 .. M*DINNER-1
    const int d = idx & (DINNER - 1);
    const int m = idx >> 11;             // DINNER = 2^11
    const int t = m & (SEQ - 1);

    float acc = conv_b[d];
    #pragma unroll
    for (int j = 0; j < DCONV; j++) {
        const int tt = t - (DCONV - 1) + j;
        if (tt >= 0) {
            acc = fmaf(conv_w[d * DCONV + j],
                       g_xz[(size_t)(m - (DCONV - 1) + j) * (2 * DINNER) + d],
                       acc);
        }
    }
    // silu
    const float s = acc / (1.f + __expf(-acc));
    g_xc[(size_t)m * DINNER + d] = s;
}

// ---------------------------------------------------------------------------
// Skinny GEMM: bdt(M,32) = xc(M,2048) @ W_x(2048,32)
// Block (32,8): lane j = output column, warp row = one m each.
// ---------------------------------------------------------------------------
__global__ __launch_bounds__(256)
void bdt_kernel(const float* __restrict__ W_x)
{
    const int j = threadIdx.x;                       // 0..31
    const int m = blockIdx.x * 8 + threadIdx.y;      // 0..8191
    const float* xrow = g_xc + (size_t)m * DINNER;

    float acc = 0.f;
    #pragma unroll 8
    for (int k = 0; k < DINNER; k++)
        acc = fmaf(xrow[k], W_x[k * 32 + j], acc);

    g_bdt[(size_t)m * 32 + j] = acc;
}

// ---------------------------------------------------------------------------
// Selective scan. One thread per (b, d, n); h lives in a register the whole
// sequence. 16-lane shuffle reduction for y = sum_n h*C. Lane n==0 fuses the
// D skip connection and the silu(z) gate, writing u = (y + xc*D) * silu(z).
// ---------------------------------------------------------------------------
__global__ __launch_bounds__(256)
void scan_kernel(const float* __restrict__ A_log,
                 const float* __restrict__ D_param)
{
    const int tid = blockIdx.x * blockDim.x + threadIdx.x; // 0 .. 131071
    const int n = tid & (DSTATE - 1);
    const int d = (tid >> 4) & (DINNER - 1);
    const int b = tid >> 15;                 // DINNER*DSTATE = 2^15

    const float Aneg = -expf(A_log[d * DSTATE + n]);   // A = -exp(A_log)
    const float Dp   = D_param[d];

    const int base_x   = b * (SEQ * DINNER) + d;             // g_xc/g_dt/g_u
    const int base_bdt = b * (SEQ * 2 * DSTATE);
    const int base_z   = b * (SEQ * 2 * DINNER) + DINNER + d; // z half of g_xz

    float h = 0.f;
    for (int t = 0; t < SEQ; t++) {
        const float xv  = g_xc[base_x + t * DINNER];
        const float dtv = g_dt[base_x + t * DINNER];
        const float Bv  = g_bdt[base_bdt + t * 32 + n];
        const float Cv  = g_bdt[base_bdt + t * 32 + DSTATE + n];

        const float dA = __expf(dtv * Aneg);
        h = fmaf(dA, h, dtv * xv * Bv);

        float p = h * Cv;
        p += __shfl_xor_sync(0xffffffffu, p, 1);
        p += __shfl_xor_sync(0xffffffffu, p, 2);
        p += __shfl_xor_sync(0xffffffffu, p, 4);
        p += __shfl_xor_sync(0xffffffffu, p, 8);

        if (n == 0) {
            const float zv = g_xz[base_z + t * (2 * DINNER)];
            const float y  = fmaf(xv, Dp, p);
            const float u  = y * (zv / (1.f + __expf(-zv)));
            g_u[base_x + t * DINNER] = u;
        }
    }
}

// ---------------------------------------------------------------------------
// Host launch
// ---------------------------------------------------------------------------
extern "C" void kernel_launch(void* const* d_in, const int* in_sizes, int n_in,
                              void* d_out, int out_size)
{
    const float* x      = (const float*)d_in[0]; // (4,2048,1024)
    const float* W_in   = (const float*)d_in[1]; // (1024,4096)
    const float* conv_w = (const float*)d_in[2]; // (2048,1,4)
    const float* conv_b = (const float*)d_in[3]; // (2048)
    const float* W_x    = (const float*)d_in[4]; // (2048,32)
    const float* W_dt   = (const float*)d_in[5]; // (2048,2048)
    const float* b_dt   = (const float*)d_in[6]; // (2048)
    const float* W_out  = (const float*)d_in[7]; // (2048,1024)
    const float* A_log  = (const float*)d_in[8]; // (2048,16)
    const float* D_par  = (const float*)d_in[9]; // (2048)
    float* out = (float*)d_out;                  // (4,2048,1024)

    float *p_xz, *p_xc, *p_dt, *p_u;
    cudaGetSymbolAddress((void**)&p_xz, g_xz);
    cudaGetSymbolAddress((void**)&p_xc, g_xc);
    cudaGetSymbolAddress((void**)&p_dt, g_dt);
    cudaGetSymbolAddress((void**)&p_u,  g_u);

    // 1) xz = x @ W_in                         (8192 x 1024 x 4096)
    {
        dim3 grid((2 * DINNER) / 128, MROWS / 128);
        gemm_kernel<0><<<grid, 256>>>(x, W_in, p_xz, MROWS, 2 * DINNER, DMODEL, nullptr);
    }
    // 2) xc = silu(causal depthwise conv(x_inner) + b)
    {
        const int total = MROWS * DINNER;
        conv_silu_kernel<<<total / 256, 256>>>(conv_w, conv_b);
    }
    // 3) bdt = xc @ W_x                        (8192 x 2048 x 32)
    {
        dim3 block(32, 8);
        bdt_kernel<<<MROWS / 8, block>>>(W_x);
    }
    // 4) dt = softplus(xc @ W_dt + b_dt)       (8192 x 2048 x 2048)
    {
        dim3 grid(DINNER / 128, MROWS / 128);
        gemm_kernel<1><<<grid, 256>>>(p_xc, W_dt, p_dt, MROWS, DINNER, DINNER, b_dt);
    }
    // 5) selective scan -> u = (y + xc*D) * silu(z)
    {
        const int total = BATCH * DINNER * DSTATE;   // 131072
        scan_kernel<<<total / 256, 256>>>(A_log, D_par);
    }
    // 6) out = u @ W_out                       (8192 x 2048 x 1024)
    {
        dim3 grid(DMODEL / 128, MROWS / 128);
        gemm_kernel<0><<<grid, 256>>>(p_u, W_out, out, MROWS, DMODEL, DINNER, nullptr);
    }
}

// round 6
// speedup vs baseline: 1.7092x; 1.7092x over previous
#include <cuda_runtime.h>
#include <cuda_bf16.h>
#include <math.h>
#include <stdint.h>

// ---------------------------------------------------------------------------
// Problem constants
// ---------------------------------------------------------------------------
#define BATCH   4
#define SEQ     2048
#define DMODEL  1024
#define DINNER  2048
#define DSTATE  16
#define DCONV   4
#define MROWS   (BATCH * SEQ)          // 8192

// ---------------------------------------------------------------------------
// Scratch (static device globals; allocation-free per harness rules)
// ---------------------------------------------------------------------------
__device__ __align__(16) float g_xz [MROWS * 2 * DINNER];   // (8192, 4096)
__device__ __align__(16) float g_xc [MROWS * DINNER];       // (8192, 2048)
__device__ __align__(16) float g_dt [MROWS * DINNER];       // (8192, 2048)
__device__ __align__(16) float g_bdt[MROWS * 2 * DSTATE];   // (8192, 32)
__device__ __align__(16) float g_u  [MROWS * DINNER];       // (8192, 2048)
// transposed weights [N, K]
__device__ __align__(16) float g_wt_in [(2 * DINNER) * DMODEL]; // (4096,1024)
__device__ __align__(16) float g_wt_dt [DINNER * DINNER];       // (2048,2048)
__device__ __align__(16) float g_wt_out[DMODEL * DINNER];       // (1024,2048)

// ---------------------------------------------------------------------------
// Helpers
// ---------------------------------------------------------------------------
__device__ __forceinline__ uint32_t smem_u32(const void* p) {
    uint32_t a;
    asm("{ .reg .u64 t; cvta.to.shared.u64 t, %1; cvt.u32.u64 %0, t; }"
        : "=r"(a) : "l"(p));
    return a;
}

// split two floats into packed bf16 hi pair + lo (residual) pair
__device__ __forceinline__ void split2(float x, float y,
                                       uint32_t& hi, uint32_t& lo) {
    __nv_bfloat16 bx = __float2bfloat16_rn(x);
    __nv_bfloat16 by = __float2bfloat16_rn(y);
    float rx = x - __bfloat162float(bx);
    float ry = y - __bfloat162float(by);
    __nv_bfloat16 lx = __float2bfloat16_rn(rx);
    __nv_bfloat16 ly = __float2bfloat16_rn(ry);
    hi = (uint32_t)__bfloat16_as_ushort(bx) |
         ((uint32_t)__bfloat16_as_ushort(by) << 16);
    lo = (uint32_t)__bfloat16_as_ushort(lx) |
         ((uint32_t)__bfloat16_as_ushort(ly) << 16);
}

// split a float4 and store hi/lo 8-byte pairs to shared memory
__device__ __forceinline__ void sts_split4(uint32_t hi_addr, uint32_t lo_addr,
                                           float4 v) {
    uint32_t h0, l0, h1, l1;
    split2(v.x, v.y, h0, l0);
    split2(v.z, v.w, h1, l1);
    asm volatile("st.shared.v2.b32 [%0], {%1,%2};"
                 :: "r"(hi_addr), "r"(h0), "r"(h1) : "memory");
    asm volatile("st.shared.v2.b32 [%0], {%1,%2};"
                 :: "r"(lo_addr), "r"(l0), "r"(l1) : "memory");
}

__device__ __forceinline__ void ldm_x4(uint32_t addr, uint32_t r[4]) {
    asm volatile("ldmatrix.sync.aligned.m8n8.x4.shared.b16 {%0,%1,%2,%3}, [%4];"
                 : "=r"(r[0]), "=r"(r[1]), "=r"(r[2]), "=r"(r[3])
                 : "r"(addr));
}

__device__ __forceinline__ void mma_bf16(float d[4], const uint32_t a[4],
                                         uint32_t b0, uint32_t b1) {
    asm volatile(
        "mma.sync.aligned.m16n8k16.row.col.f32.bf16.bf16.f32 "
        "{%0,%1,%2,%3}, {%4,%5,%6,%7}, {%8,%9}, {%0,%1,%2,%3};"
        : "+f"(d[0]), "+f"(d[1]), "+f"(d[2]), "+f"(d[3])
        : "r"(a[0]), "r"(a[1]), "r"(a[2]), "r"(a[3]), "r"(b0), "r"(b1));
}

// ---------------------------------------------------------------------------
// Split-bf16 tensor-core GEMM:  C(M,N) = A(M,K) @ Bt(N,K)^T
// 128x128 CTA tile, BK=16, 256 thr, 8 warps (2M x 4N), warp tile 64x32.
// 3 mma passes per K-step: ah*bh + ah*bl + al*bh  (~1e-5 relative accuracy).
// Smem rows padded to 48B -> conflict-free ldmatrix. Double-buffered stages.
// MODE 0: plain store.  MODE 1: softplus(acc + bias[n]).
// ---------------------------------------------------------------------------
#define STG_BYTES 24576            // 4 arrays * 128 rows * 48B
#define ROW_B     48               // padded row stride in bytes (16 bf16 + pad)
#define OFF_AL    6144
#define OFF_BH    12288
#define OFF_BL    18432

template<int MODE>
__global__ __launch_bounds__(256)
void gemm_mma(const float* __restrict__ A, const float* __restrict__ Bt,
              float* __restrict__ C, int K, int N, const float* __restrict__ bias)
{
    __shared__ __align__(16) unsigned char smem[2 * STG_BYTES];
    const uint32_t sb = smem_u32(smem);

    const int tid  = threadIdx.x;
    const int lane = tid & 31;
    const int wid  = tid >> 5;
    const int wm   = wid >> 2;          // 0..1  (M)
    const int wn   = wid & 3;           // 0..3  (N)
    const int m0   = blockIdx.y * 128;
    const int n0   = blockIdx.x * 128;

    // ---- global loader mapping: 512 float4 per (A or B) tile, 2 per thread
    const int ar0 = tid >> 2,          ac0 = tid & 3;
    const int ar1 = (tid + 256) >> 2,  ac1 = (tid + 256) & 3;
    const uint32_t so0 = (uint32_t)(ar0 * ROW_B + ac0 * 8);
    const uint32_t so1 = (uint32_t)(ar1 * ROW_B + ac1 * 8);
    const float* ApA0 = A  + (size_t)(m0 + ar0) * K + ac0 * 4;
    const float* ApA1 = A  + (size_t)(m0 + ar1) * K + ac1 * 4;
    const float* ApB0 = Bt + (size_t)(n0 + ar0) * K + ac0 * 4;
    const float* ApB1 = Bt + (size_t)(n0 + ar1) * K + ac1 * 4;

    // ---- ldmatrix lane address offsets
    const uint32_t la = (uint32_t)((lane & 15) * ROW_B + (lane >> 4) * 16);
    const uint32_t lb = (uint32_t)(((((lane >> 4) << 3) + (lane & 7)) * ROW_B) +
                                   ((lane >> 3) & 1) * 16);

    float acc[4][4][4];
    #pragma unroll
    for (int f = 0; f < 4; f++)
        #pragma unroll
        for (int g = 0; g < 4; g++)
            #pragma unroll
            for (int r = 0; r < 4; r++) acc[f][g][r] = 0.f;

    const int KT = K >> 4;

    float4 va0 = *(const float4*)ApA0;
    float4 va1 = *(const float4*)ApA1;
    float4 vb0 = *(const float4*)ApB0;
    float4 vb1 = *(const float4*)ApB1;

    for (int kt = 0; kt < KT; kt++) {
        const uint32_t st = sb + (uint32_t)(kt & 1) * STG_BYTES;

        // stage (with on-the-fly hi/lo split)
        sts_split4(st +          so0, st + OFF_AL + so0, va0);
        sts_split4(st +          so1, st + OFF_AL + so1, va1);
        sts_split4(st + OFF_BH + so0, st + OFF_BL + so0, vb0);
        sts_split4(st + OFF_BH + so1, st + OFF_BL + so1, vb1);
        __syncthreads();

        // prefetch next K-tile
        if (kt + 1 < KT) {
            const int ko = (kt + 1) * 16;
            va0 = *(const float4*)(ApA0 + ko);
            va1 = *(const float4*)(ApA1 + ko);
            vb0 = *(const float4*)(ApB0 + ko);
            vb1 = *(const float4*)(ApB1 + ko);
        }

        // compute
        const uint32_t aAh = st + (uint32_t)(wm * 64 * ROW_B) + la;
        const uint32_t aBh = st + OFF_BH + (uint32_t)(wn * 32 * ROW_B) + lb;

        uint32_t ah[4][4], bh[2][4], blr[2][4];
        #pragma unroll
        for (int f = 0; f < 4; f++) ldm_x4(aAh + f * (16 * ROW_B), ah[f]);
        #pragma unroll
        for (int p = 0; p < 2; p++) ldm_x4(aBh + p * (16 * ROW_B), bh[p]);

        #pragma unroll
        for (int f = 0; f < 4; f++)
            #pragma unroll
            for (int g = 0; g < 4; g++)
                mma_bf16(acc[f][g], ah[f], bh[g >> 1][(g & 1) * 2],
                         bh[g >> 1][(g & 1) * 2 + 1]);

        #pragma unroll
        for (int p = 0; p < 2; p++)
            ldm_x4(aBh + OFF_BL - OFF_BH + p * (16 * ROW_B), blr[p]);

        #pragma unroll
        for (int f = 0; f < 4; f++)
            #pragma unroll
            for (int g = 0; g < 4; g++)
                mma_bf16(acc[f][g], ah[f], blr[g >> 1][(g & 1) * 2],
                         blr[g >> 1][(g & 1) * 2 + 1]);

        #pragma unroll
        for (int f = 0; f < 4; f++) ldm_x4(aAh + OFF_AL + f * (16 * ROW_B), ah[f]);

        #pragma unroll
        for (int f = 0; f < 4; f++)
            #pragma unroll
            for (int g = 0; g < 4; g++)
                mma_bf16(acc[f][g], ah[f], bh[g >> 1][(g & 1) * 2],
                         bh[g >> 1][(g & 1) * 2 + 1]);
    }

    // ---- epilogue: registers -> global
    const int gid = lane >> 2;
    const int qid = lane & 3;
    #pragma unroll
    for (int f = 0; f < 4; f++) {
        #pragma unroll
        for (int g = 0; g < 4; g++) {
            const int m  = m0 + wm * 64 + f * 16 + gid;
            const int nn = n0 + wn * 32 + g * 8 + qid * 2;
            float2 v0 = make_float2(acc[f][g][0], acc[f][g][1]);
            float2 v1 = make_float2(acc[f][g][2], acc[f][g][3]);
            if (MODE == 1) {
                const float b0v = bias[nn], b1v = bias[nn + 1];
                v0.x += b0v; v0.y += b1v; v1.x += b0v; v1.y += b1v;
                v0.x = (v0.x > 20.f) ? v0.x : log1pf(expf(v0.x));
                v0.y = (v0.y > 20.f) ? v0.y : log1pf(expf(v0.y));
                v1.x = (v1.x > 20.f) ? v1.x : log1pf(expf(v1.x));
                v1.y = (v1.y > 20.f) ? v1.y : log1pf(expf(v1.y));
            }
            *(float2*)(C + (size_t)m * N + nn)       = v0;
            *(float2*)(C + (size_t)(m + 8) * N + nn) = v1;
        }
    }
}

// ---------------------------------------------------------------------------
// Weight transpose: Wt(N,K) = W(K,N).  32x32 smem tiles, block (32,8).
// ---------------------------------------------------------------------------
__global__ __launch_bounds__(256)
void transpose_kernel(const float* __restrict__ W, float* __restrict__ Wt,
                      int K, int N)
{
    __shared__ float t[32][33];
    const int n0 = blockIdx.x * 32, k0 = blockIdx.y * 32;
    const int x = threadIdx.x, y = threadIdx.y;
    #pragma unroll
    for (int i = 0; i < 32; i += 8)
        t[y + i][x] = W[(size_t)(k0 + y + i) * N + n0 + x];
    __syncthreads();
    #pragma unroll
    for (int i = 0; i < 32; i += 8)
        Wt[(size_t)(n0 + y + i) * K + k0 + x] = t[x][y + i];
}

// ---------------------------------------------------------------------------
// Causal depthwise conv1d (k=4) + bias + SiLU over x_inner = g_xz[:, :2048]
// ---------------------------------------------------------------------------
__global__ __launch_bounds__(256)
void conv_silu_kernel(const float* __restrict__ conv_w,
                      const float* __restrict__ conv_b)
{
    const int idx = blockIdx.x * blockDim.x + threadIdx.x;
    const int d = idx & (DINNER - 1);
    const int m = idx >> 11;
    const int t = m & (SEQ - 1);

    float acc = conv_b[d];
    #pragma unroll
    for (int j = 0; j < DCONV; j++) {
        const int tt = t - (DCONV - 1) + j;
        if (tt >= 0) {
            acc = fmaf(conv_w[d * DCONV + j],
                       g_xz[(size_t)(m - (DCONV - 1) + j) * (2 * DINNER) + d],
                       acc);
        }
    }
    const float s = acc / (1.f + __expf(-acc));
    g_xc[(size_t)m * DINNER + d] = s;
}

// ---------------------------------------------------------------------------
// Skinny GEMM: bdt(M,32) = xc(M,2048) @ W_x(2048,32)
// ---------------------------------------------------------------------------
__global__ __launch_bounds__(256)
void bdt_kernel(const float* __restrict__ W_x)
{
    const int j = threadIdx.x;                       // 0..31
    const int m = blockIdx.x * 8 + threadIdx.y;
    const float* xrow = g_xc + (size_t)m * DINNER;

    float acc = 0.f;
    #pragma unroll 8
    for (int k = 0; k < DINNER; k++)
        acc = fmaf(xrow[k], W_x[k * 32 + j], acc);

    g_bdt[(size_t)m * 32 + j] = acc;
}

// ---------------------------------------------------------------------------
// Selective scan: one thread per (b,d,n), 16-lane shuffle reduction;
// fuses D-skip and silu(z) gate: u = (y + xc*D) * silu(z)
// ---------------------------------------------------------------------------
__global__ __launch_bounds__(256)
void scan_kernel(const float* __restrict__ A_log,
                 const float* __restrict__ D_param)
{
    const int tid = blockIdx.x * blockDim.x + threadIdx.x;
    const int n = tid & (DSTATE - 1);
    const int d = (tid >> 4) & (DINNER - 1);
    const int b = tid >> 15;

    const float Aneg = -expf(A_log[d * DSTATE + n]);
    const float Dp   = D_param[d];

    const int base_x   = b * (SEQ * DINNER) + d;
    const int base_bdt = b * (SEQ * 2 * DSTATE);
    const int base_z   = b * (SEQ * 2 * DINNER) + DINNER + d;

    float h = 0.f;
    for (int t = 0; t < SEQ; t++) {
        const float xv  = g_xc[base_x + t * DINNER];
        const float dtv = g_dt[base_x + t * DINNER];
        const float Bv  = g_bdt[base_bdt + t * 32 + n];
        const float Cv  = g_bdt[base_bdt + t * 32 + DSTATE + n];

        const float dA = __expf(dtv * Aneg);
        h = fmaf(dA, h, dtv * xv * Bv);

        float p = h * Cv;
        p += __shfl_xor_sync(0xffffffffu, p, 1);
        p += __shfl_xor_sync(0xffffffffu, p, 2);
        p += __shfl_xor_sync(0xffffffffu, p, 4);
        p += __shfl_xor_sync(0xffffffffu, p, 8);

        if (n == 0) {
            const float zv = g_xz[base_z + t * (2 * DINNER)];
            const float y  = fmaf(xv, Dp, p);
            const float u  = y * (zv / (1.f + __expf(-zv)));
            g_u[base_x + t * DINNER] = u;
        }
    }
}

// ---------------------------------------------------------------------------
// Host launch
// ---------------------------------------------------------------------------
extern "C" void kernel_launch(void* const* d_in, const int* in_sizes, int n_in,
                              void* d_out, int out_size)
{
    const float* x      = (const float*)d_in[0]; // (4,2048,1024)
    const float* W_in   = (const float*)d_in[1]; // (1024,4096)
    const float* conv_w = (const float*)d_in[2]; // (2048,1,4)
    const float* conv_b = (const float*)d_in[3]; // (2048)
    const float* W_x    = (const float*)d_in[4]; // (2048,32)
    const float* W_dt   = (const float*)d_in[5]; // (2048,2048)
    const float* b_dt   = (const float*)d_in[6]; // (2048)
    const float* W_out  = (const float*)d_in[7]; // (2048,1024)
    const float* A_log  = (const float*)d_in[8]; // (2048,16)
    const float* D_par  = (const float*)d_in[9]; // (2048)
    float* out = (float*)d_out;                  // (4,2048,1024)

    float *p_xz, *p_xc, *p_dt, *p_u, *p_wt_in, *p_wt_dt, *p_wt_out;
    cudaGetSymbolAddress((void**)&p_xz,     g_xz);
    cudaGetSymbolAddress((void**)&p_xc,     g_xc);
    cudaGetSymbolAddress((void**)&p_dt,     g_dt);
    cudaGetSymbolAddress((void**)&p_u,      g_u);
    cudaGetSymbolAddress((void**)&p_wt_in,  g_wt_in);
    cudaGetSymbolAddress((void**)&p_wt_dt,  g_wt_dt);
    cudaGetSymbolAddress((void**)&p_wt_out, g_wt_out);

    // 0) transpose weights to [N, K]
    {
        dim3 blk(32, 8);
        transpose_kernel<<<dim3((2*DINNER)/32, DMODEL/32), blk>>>(W_in,  p_wt_in,  DMODEL, 2*DINNER);
        transpose_kernel<<<dim3(DINNER/32,     DINNER/32), blk>>>(W_dt,  p_wt_dt,  DINNER, DINNER);
        transpose_kernel<<<dim3(DMODEL/32,     DINNER/32), blk>>>(W_out, p_wt_out, DINNER, DMODEL);
    }
    // 1) xz = x @ W_in       (M=8192, N=4096, K=1024)
    gemm_mma<0><<<dim3((2*DINNER)/128, MROWS/128), 256>>>(
        x, p_wt_in, p_xz, DMODEL, 2*DINNER, nullptr);
    // 2) xc = silu(conv(x_inner) + b)
    conv_silu_kernel<<<(MROWS * DINNER) / 256, 256>>>(conv_w, conv_b);
    // 3) bdt = xc @ W_x      (M=8192, N=32, K=2048)
    {
        dim3 block(32, 8);
        bdt_kernel<<<MROWS / 8, block>>>(W_x);
    }
    // 4) dt = softplus(xc @ W_dt + b_dt)   (M=8192, N=2048, K=2048)
    gemm_mma<1><<<dim3(DINNER/128, MROWS/128), 256>>>(
        p_xc, p_wt_dt, p_dt, DINNER, DINNER, b_dt);
    // 5) selective scan -> u
    scan_kernel<<<(BATCH * DINNER * DSTATE) / 256, 256>>>(A_log, D_par);
    // 6) out = u @ W_out     (M=8192, N=1024, K=2048)
    gemm_mma<0><<<dim3(DMODEL/128, MROWS/128), 256>>>(
        p_u, p_wt_out, out, DINNER, DMODEL, nullptr);
}